// round 17
// baseline (speedup 1.0000x reference)
#include <cuda_runtime.h>
#include <cuda_bf16.h>
#include <cuda_fp16.h>
#include <cstdint>
#include <math.h>

#define EMBED   1024
#define HEADS   16
#define HD      64
#define BATCH   2
#define SEQ     2048
#define MROWS   (BATCH*SEQ)       /* 4096 */
#define NQKV    (3*EMBED)         /* 3072 */
#define LOG2E   1.44269504088896f

/* ---------------- scratch (__device__ globals) ------------------------- */
__device__ __half g_Qf[BATCH*HEADS*SEQ*HD];   /* pre-scaled by 0.125*log2e */
__device__ __half g_Kf[BATCH*HEADS*SEQ*HD];
__device__ __half g_Vf[BATCH*HEADS*SEQ*HD];

__device__ __half g_Xf[MROWS*EMBED];          /* activations, fp16 */
__device__ __half g_Af[MROWS*EMBED];          /* attention output, fp16 */
__device__ __half g_Wh[NQKV*EMBED];           /* qkv_w, fp16 */
__device__ __half g_Ph[EMBED*EMBED];          /* proj_w, fp16 */

/* ---------------- helpers ---------------------------------------------- */
__device__ __forceinline__ uint32_t smem_u32(const void* p) {
    uint32_t a;
    asm("{ .reg .u64 t; cvta.to.shared.u64 t, %1; cvt.u32.u64 %0, t; }"
        : "=r"(a) : "l"(p));
    return a;
}
__device__ __forceinline__ void cp16(uint32_t dst, const void* src) {
    asm volatile("cp.async.cg.shared.global [%0], [%1], 16;" :: "r"(dst), "l"(src));
}
#define CP_COMMIT() asm volatile("cp.async.commit_group;" ::: "memory")
#define CP_WAIT(n)  asm volatile("cp.async.wait_group %0;" :: "n"(n) : "memory")

__device__ __forceinline__ void ldm_x4(uint32_t& r0, uint32_t& r1,
                                       uint32_t& r2, uint32_t& r3, uint32_t addr) {
    asm volatile("ldmatrix.sync.aligned.m8n8.x4.shared.b16 {%0,%1,%2,%3}, [%4];"
                 : "=r"(r0), "=r"(r1), "=r"(r2), "=r"(r3) : "r"(addr));
}
__device__ __forceinline__ void ldm_x4_t(uint32_t& r0, uint32_t& r1,
                                         uint32_t& r2, uint32_t& r3, uint32_t addr) {
    asm volatile("ldmatrix.sync.aligned.m8n8.x4.trans.shared.b16 {%0,%1,%2,%3}, [%4];"
                 : "=r"(r0), "=r"(r1), "=r"(r2), "=r"(r3) : "r"(addr));
}
__device__ __forceinline__ void mma_f16(float* c, const uint32_t* a,
                                        uint32_t b0, uint32_t b1) {
    asm volatile("mma.sync.aligned.m16n8k16.row.col.f32.f16.f16.f32 "
                 "{%0,%1,%2,%3}, {%4,%5,%6,%7}, {%8,%9}, {%0,%1,%2,%3};"
                 : "+f"(c[0]), "+f"(c[1]), "+f"(c[2]), "+f"(c[3])
                 : "r"(a[0]), "r"(a[1]), "r"(a[2]), "r"(a[3]), "r"(b0), "r"(b1));
}
/* single-instruction MUFU exp2 (exp2f w/o fast-math is a ~20-instr routine) */
__device__ __forceinline__ float ex2(float x) {
    float y;
    asm("ex2.approx.ftz.f32 %0, %1;" : "=f"(y) : "f"(x));
    return y;
}
__device__ __forceinline__ uint32_t swz64(uint32_t o)  { return o ^ ((o >> 3) & 0x30); }
__device__ __forceinline__ uint32_t swz128(uint32_t o) { return o ^ ((o >> 3) & 0x70); }

/* ---------------- fused conversion kernel ------------------------------- */
#define NX (MROWS*EMBED/4)
#define NW (NQKV*EMBED/4)
#define NP (EMBED*EMBED/4)
__global__ __launch_bounds__(256) void conv_all(const float* __restrict__ x,
                                                const float* __restrict__ qkv_w,
                                                const float* __restrict__ proj_w)
{
    for (int i = blockIdx.x * 256 + threadIdx.x; i < NX + NW + NP;
         i += gridDim.x * 256) {
        const float4* src;
        __half2* dst;
        int j;
        if (i < NX)           { src = (const float4*)x;      dst = (__half2*)g_Xf; j = i; }
        else if (i < NX + NW) { src = (const float4*)qkv_w;  dst = (__half2*)g_Wh; j = i - NX; }
        else                  { src = (const float4*)proj_w; dst = (__half2*)g_Ph; j = i - NX - NW; }
        float4 v = src[j];
        dst[j*2+0] = __floats2half2_rn(v.x, v.y);
        dst[j*2+1] = __floats2half2_rn(v.z, v.w);
    }
}

/* ---------------- warp-MMA fp16 GEMM (3-stage pipeline) ----------------- */
#define BK      32
#define NCHG    (1024/BK)              /* 32 */
#define TILE_B  8192
#define STAGE   (2*TILE_B)             /* 16KB */
#define GEMM_SMEM (3*STAGE)            /* 49152 */

template<int MODE>
__global__ __launch_bounds__(256) void gemm_mma(const float* __restrict__ bias,
                                                float* __restrict__ out)
{
    extern __shared__ char smem_raw[];
    const int tid = threadIdx.x, wid = tid >> 5, lane = tid & 31;
    const int bm = blockIdx.y * 128, bn = blockIdx.x * 128;

    const __half* Ap = (MODE == 0) ? g_Xf : g_Af;
    const __half* Bp = (MODE == 0) ? g_Wh : g_Ph;

    const uint32_t sbase = smem_u32(smem_raw);

    const int lr0 = tid >> 2;               /* rows 0..63 (i=0) */
    const int lu  = tid & 3;                /* 16B unit 0..3    */

    const int wm = (wid >> 2) * 64;
    const int wn = (wid & 3) * 32;

    const int a_r = wm + (lane & 15);
    const int b_r = wn + (lane & 7) + ((lane >> 4) << 3);
    const uint32_t a_base = (uint32_t)(a_r * 64 + ((lane >> 4) << 4));
    const uint32_t b_base = (uint32_t)(b_r * 64 + (((lane >> 3) & 1) << 4));

    float acc[4][4][4];
#pragma unroll
    for (int mt = 0; mt < 4; mt++)
#pragma unroll
        for (int nt = 0; nt < 4; nt++)
#pragma unroll
            for (int i = 0; i < 4; i++) acc[mt][nt][i] = 0.f;

    auto load_chunk = [&](int stage, int k0) {
        const uint32_t sb = sbase + stage * STAGE;
#pragma unroll
        for (int i = 0; i < 2; i++) {
            const int r = lr0 + i * 64;
            const uint32_t so = swz64((uint32_t)(r * 64 + lu * 16));
            cp16(sb + so,          Ap + (size_t)(bm + r) * 1024 + k0 + lu * 8);
            cp16(sb + TILE_B + so, Bp + (size_t)(bn + r) * 1024 + k0 + lu * 8);
        }
    };

    load_chunk(0, 0);
    CP_COMMIT();
    load_chunk(1, BK);
    CP_COMMIT();

    int stage = 0;
    for (int c = 0; c < NCHG; c++) {
        if (c + 2 < NCHG) {
            int s2 = stage + 2;
            if (s2 >= 3) s2 -= 3;
            load_chunk(s2, (c + 2) * BK);
            CP_COMMIT();
            CP_WAIT(2);
        } else if (c + 1 < NCHG) {
            CP_WAIT(1);
        } else {
            CP_WAIT(0);
        }
        __syncthreads();

        const uint32_t sb = sbase + stage * STAGE;
#pragma unroll
        for (int ks = 0; ks < 2; ks++) {
            uint32_t ah[4][4], bh[2][4];
#pragma unroll
            for (int mt = 0; mt < 4; mt++) {
                const uint32_t off = swz64(a_base + (uint32_t)(mt*16*64 + ks*32));
                ldm_x4(ah[mt][0], ah[mt][1], ah[mt][2], ah[mt][3], sb + off);
            }
#pragma unroll
            for (int np = 0; np < 2; np++) {
                const uint32_t off = swz64(b_base + (uint32_t)(np*16*64 + ks*32));
                ldm_x4(bh[np][0], bh[np][1], bh[np][2], bh[np][3], sb + TILE_B + off);
            }
#pragma unroll
            for (int mt = 0; mt < 4; mt++)
#pragma unroll
                for (int nt = 0; nt < 4; nt++) {
                    const int np = nt >> 1, h = (nt & 1) * 2;
                    mma_f16(acc[mt][nt], ah[mt], bh[np][h], bh[np][h+1]);
                }
        }
        __syncthreads();
        stage = (stage == 2) ? 0 : stage + 1;
    }

    const int gr = lane >> 2, cp = (lane & 3) * 2;
    const float QSCL = 0.125f * LOG2E;
#pragma unroll
    for (int mt = 0; mt < 4; mt++) {
        const int m0 = bm + wm + mt*16 + gr;
#pragma unroll
        for (int half = 0; half < 2; half++) {
            const int m = m0 + half * 8;
#pragma unroll
            for (int nt = 0; nt < 4; nt++) {
                const int n = bn + wn + nt*8 + cp;
                float2 v;
                v.x = acc[mt][nt][half*2 + 0];
                v.y = acc[mt][nt][half*2 + 1];
                if (MODE == 0) {
                    const int b = m >> 11, s = m & 2047;
                    const int part = n >> 10, hh = (n >> 6) & 15, dd = n & 63;
                    const size_t idx = (((size_t)(b*HEADS + hh))*SEQ + s)*HD + dd;
                    if (part == 0) {
                        *(__half2*)(g_Qf + idx) = __floats2half2_rn(v.x*QSCL, v.y*QSCL);
                    } else if (part == 1) {
                        *(__half2*)(g_Kf + idx) = __floats2half2_rn(v.x, v.y);
                    } else {
                        *(__half2*)(g_Vf + idx) = __floats2half2_rn(v.x, v.y);
                    }
                } else {
                    v.x += bias[n]; v.y += bias[n+1];
                    *(float2*)(out + (size_t)m * 1024 + n) = v;
                }
            }
        }
    }
}

/* ---------------- fp16 tensor-core flash attention ---------------------- */
__global__ __launch_bounds__(256, 2) void attn_tc()
{
    __shared__ char kvs[2][2][64*128];     /* [stage][K|V][64 rows x 128B] */

    const int tid = threadIdx.x, wid = tid >> 5, lane = tid & 31;
    const int g = lane >> 2, qd = lane & 3;
    const int bh = blockIdx.y;
    const int q0 = blockIdx.x * 128 + wid * 16;
    const size_t base = (size_t)bh * SEQ * HD;

    uint32_t qa[4][4];
    {
        const __half* Qp = g_Qf + base;
        const int r0 = q0 + g, r1 = q0 + g + 8;
#pragma unroll
        for (int ks = 0; ks < 4; ks++) {
            qa[ks][0] = *(const uint32_t*)(Qp + (size_t)r0*64 + ks*16 + 2*qd);
            qa[ks][1] = *(const uint32_t*)(Qp + (size_t)r1*64 + ks*16 + 2*qd);
            qa[ks][2] = *(const uint32_t*)(Qp + (size_t)r0*64 + ks*16 + 8 + 2*qd);
            qa[ks][3] = *(const uint32_t*)(Qp + (size_t)r1*64 + ks*16 + 8 + 2*qd);
        }
    }

    float o[8][4];
#pragma unroll
    for (int j = 0; j < 8; j++)
#pragma unroll
        for (int i = 0; i < 4; i++) o[j][i] = 0.f;
    float m0 = -1e30f, m1 = -1e30f, l0 = 0.f, l1 = 0.f;

    auto load_kv = [&](int s, int t) {
        const __half* Kg = g_Kf + base + (size_t)t * 64 * 64;
        const __half* Vg = g_Vf + base + (size_t)t * 64 * 64;
        const uint32_t kb = smem_u32(&kvs[s][0][0]);
        const uint32_t vb = smem_u32(&kvs[s][1][0]);
#pragma unroll
        for (int i = 0; i < 2; i++) {
            const int idx = tid + i * 256;
            const int r = idx >> 3, u = idx & 7;
            const uint32_t off = swz128((uint32_t)(r * 128 + u * 16));
            cp16(kb + off, Kg + r * 64 + u * 8);
            cp16(vb + off, Vg + r * 64 + u * 8);
        }
    };

    const int krow_in = (lane & 7) + ((lane >> 4) << 3);
    const uint32_t kunit = ((lane >> 3) & 1) * 16;
    const int vrow_in = (lane & 7) + (((lane >> 3) & 1) << 3);
    const uint32_t vunit = (lane >> 4) << 4;

    load_kv(0, 0);
    CP_COMMIT();

    for (int t = 0; t < SEQ/64; t++) {
        if (t + 1 < SEQ/64) {
            load_kv((t + 1) & 1, t + 1);
            CP_COMMIT();
            CP_WAIT(1);
        } else {
            CP_WAIT(0);
        }
        __syncthreads();

        const uint32_t kb = smem_u32(&kvs[t & 1][0][0]);
        const uint32_t vb = smem_u32(&kvs[t & 1][1][0]);

        float sc[8][4];
#pragma unroll
        for (int j = 0; j < 8; j++)
#pragma unroll
            for (int i = 0; i < 4; i++) sc[j][i] = 0.f;

#pragma unroll
        for (int ks = 0; ks < 4; ks++) {
#pragma unroll
            for (int nw = 0; nw < 4; nw++) {
                uint32_t b0, b1, b2, b3;
                const int row = nw * 16 + krow_in;
                const uint32_t addr = kb + swz128((uint32_t)(row*128 + ks*32) + kunit);
                ldm_x4(b0, b1, b2, b3, addr);
                mma_f16(sc[2*nw],   qa[ks], b0, b1);
                mma_f16(sc[2*nw+1], qa[ks], b2, b3);
            }
        }

        float mx0 = m0, mx1 = m1;
#pragma unroll
        for (int j = 0; j < 8; j++) {
            mx0 = fmaxf(mx0, fmaxf(sc[j][0], sc[j][1]));
            mx1 = fmaxf(mx1, fmaxf(sc[j][2], sc[j][3]));
        }
        mx0 = fmaxf(mx0, __shfl_xor_sync(0xffffffffu, mx0, 1));
        mx0 = fmaxf(mx0, __shfl_xor_sync(0xffffffffu, mx0, 2));
        mx1 = fmaxf(mx1, __shfl_xor_sync(0xffffffffu, mx1, 1));
        mx1 = fmaxf(mx1, __shfl_xor_sync(0xffffffffu, mx1, 2));

        const float c0 = ex2(m0 - mx0);
        const float c1 = ex2(m1 - mx1);
        m0 = mx0; m1 = mx1;
        l0 *= c0;  l1 *= c1;
#pragma unroll
        for (int j = 0; j < 8; j++) {
            o[j][0] *= c0; o[j][1] *= c0;
            o[j][2] *= c1; o[j][3] *= c1;
        }

        uint32_t pa[4][4];
        float s0 = 0.f, s1 = 0.f;
#pragma unroll
        for (int j = 0; j < 8; j++) {
            const float p0 = ex2(sc[j][0] - m0);
            const float p1 = ex2(sc[j][1] - m0);
            const float p2 = ex2(sc[j][2] - m1);
            const float p3 = ex2(sc[j][3] - m1);
            s0 += p0 + p1;  s1 += p2 + p3;
            const __half2 h01 = __floats2half2_rn(p0, p1);
            const __half2 h23 = __floats2half2_rn(p2, p3);
            const int kt = j >> 1;
            if ((j & 1) == 0) {
                pa[kt][0] = *(const uint32_t*)&h01;
                pa[kt][1] = *(const uint32_t*)&h23;
            } else {
                pa[kt][2] = *(const uint32_t*)&h01;
                pa[kt][3] = *(const uint32_t*)&h23;
            }
        }
        l0 += s0; l1 += s1;

#pragma unroll
        for (int kt = 0; kt < 4; kt++) {
#pragma unroll
            for (int nf = 0; nf < 4; nf++) {
                uint32_t v0, v1, v2, v3;
                const int row = kt * 16 + vrow_in;
                const uint32_t addr = vb + swz128((uint32_t)(row*128 + nf*32) + vunit);
                ldm_x4_t(v0, v1, v2, v3, addr);
                mma_f16(o[2*nf],   pa[kt], v0, v1);
                mma_f16(o[2*nf+1], pa[kt], v2, v3);
            }
        }
        __syncthreads();
    }

    l0 += __shfl_xor_sync(0xffffffffu, l0, 1);
    l0 += __shfl_xor_sync(0xffffffffu, l0, 2);
    l1 += __shfl_xor_sync(0xffffffffu, l1, 1);
    l1 += __shfl_xor_sync(0xffffffffu, l1, 2);
    const float inv0 = 1.f / l0, inv1 = 1.f / l1;

    const int b = bh >> 4, h = bh & 15;
    const int row0 = q0 + g, row1 = q0 + g + 8;
    __half* A0 = g_Af + ((size_t)(b*SEQ + row0))*EMBED + h*HD;
    __half* A1 = g_Af + ((size_t)(b*SEQ + row1))*EMBED + h*HD;
#pragma unroll
    for (int j = 0; j < 8; j++) {
        const int d = j*8 + 2*qd;
        *(__half2*)(A0 + d) = __floats2half2_rn(o[j][0]*inv0, o[j][1]*inv0);
        *(__half2*)(A1 + d) = __floats2half2_rn(o[j][2]*inv1, o[j][3]*inv1);
    }
}

/* ---------------- launch ------------------------------------------------ */
extern "C" void kernel_launch(void* const* d_in, const int* in_sizes, int n_in,
                              void* d_out, int out_size)
{
    const float* x      = (const float*)d_in[0];
    /* d_in[1] = xpos (unused) */
    const float* qkv_w  = (const float*)d_in[2];
    const float* proj_w = (const float*)d_in[3];
    const float* proj_b = (const float*)d_in[4];
    float* out = (float*)d_out;

    conv_all<<<1184, 256>>>(x, qkv_w, proj_w);

    dim3 gq(NQKV/128, MROWS/128);          /* 24 x 32 */
    gemm_mma<0><<<gq, 256, GEMM_SMEM>>>(nullptr, nullptr);

    dim3 ga(SEQ/128, BATCH*HEADS);         /* 16 x 32 */
    attn_tc<<<ga, 256>>>();

    dim3 gp(EMBED/128, MROWS/128);         /* 8 x 32 */
    gemm_mma<1><<<gp, 256, GEMM_SMEM>>>(proj_b, out);
}